// round 1
// baseline (speedup 1.0000x reference)
#include <cuda_runtime.h>
#include <math.h>

#define BATCH_ 16
#define SEQ_ 512
#define DIM_ 2048
#define NH_ 16
#define HD_ 128
#define ROWS_ (BATCH_*SEQ_)    // 8192
#define QKVN_ (3*DIM_)         // 6144

// ---- scratch (static device globals; no runtime allocation) ----
__device__ float g_qkv[(size_t)ROWS_ * QKVN_];      // 8192*6144
__device__ float g_q[(size_t)BATCH_*NH_*SEQ_*HD_];  // [b][h][t][d]
__device__ float g_k[(size_t)BATCH_*NH_*SEQ_*HD_];
__device__ float g_v[(size_t)BATCH_*NH_*SEQ_*HD_];
__device__ float g_y[(size_t)ROWS_ * DIM_];         // attention out, (B,T,C)

// ============================================================
// SGEMM: C[M,N] = A[M,K] @ B[K,N], row-major, fp32.
// 128x128 block tile, BK=16, 256 threads, 8x8 per thread.
// M %128==0, N %128==0, K %16==0 (all true here).
// ============================================================
__global__ __launch_bounds__(256) void sgemm_kernel(
    const float* __restrict__ A, const float* __restrict__ B,
    float* __restrict__ C, int M, int N, int K)
{
    __shared__ float As[16][128];
    __shared__ float Bs[16][128];

    const int bm = blockIdx.y, bn = blockIdx.x;
    const int tid = threadIdx.x;
    const int tx = tid & 15, ty = tid >> 4;

    const float* Ab = A + (size_t)bm * 128 * K;
    const float* Bb = B + (size_t)bn * 128;

    float acc[8][8];
#pragma unroll
    for (int i = 0; i < 8; i++)
#pragma unroll
        for (int j = 0; j < 8; j++) acc[i][j] = 0.f;

    for (int kb = 0; kb < K; kb += 16) {
        // load A tile (128 rows x 16 cols), store transposed As[k][m]
#pragma unroll
        for (int i = 0; i < 2; i++) {
            int idx = tid + i * 256;           // 0..511
            int ar = idx >> 2;                  // 0..127
            int ac = (idx & 3) << 2;            // 0,4,8,12
            float4 v = *(const float4*)(Ab + (size_t)ar * K + kb + ac);
            As[ac + 0][ar] = v.x;
            As[ac + 1][ar] = v.y;
            As[ac + 2][ar] = v.z;
            As[ac + 3][ar] = v.w;
        }
        // load B tile (16 rows x 128 cols)
#pragma unroll
        for (int i = 0; i < 2; i++) {
            int idx = tid + i * 256;
            int br = idx >> 5;                  // 0..15
            int bc = (idx & 31) << 2;           // 0..124
            *(float4*)&Bs[br][bc] = *(const float4*)(Bb + (size_t)(kb + br) * N + bc);
        }
        __syncthreads();

#pragma unroll
        for (int k = 0; k < 16; k++) {
            float a[8], b[8];
            *(float4*)&a[0] = *(float4*)&As[k][ty * 8];
            *(float4*)&a[4] = *(float4*)&As[k][ty * 8 + 4];
            *(float4*)&b[0] = *(float4*)&Bs[k][tx * 8];
            *(float4*)&b[4] = *(float4*)&Bs[k][tx * 8 + 4];
#pragma unroll
            for (int i = 0; i < 8; i++)
#pragma unroll
                for (int j = 0; j < 8; j++)
                    acc[i][j] += a[i] * b[j];
        }
        __syncthreads();
    }

    float* Cb = C + (size_t)(bm * 128 + ty * 8) * N + bn * 128 + tx * 8;
#pragma unroll
    for (int i = 0; i < 8; i++) {
        *(float4*)(Cb + (size_t)i * N)     = make_float4(acc[i][0], acc[i][1], acc[i][2], acc[i][3]);
        *(float4*)(Cb + (size_t)i * N + 4) = make_float4(acc[i][4], acc[i][5], acc[i][6], acc[i][7]);
    }
}

// ============================================================
// RoPE + split qkv -> Q,K,V in [B,H,T,hd] layout.
// Q gets the 1/sqrt(hd) softmax scale folded in.
// One thread per (b,h,t,d): 2^24 threads.
// ============================================================
__global__ __launch_bounds__(256) void rope_split_kernel(
    const float* __restrict__ qkv,
    float* __restrict__ Q, float* __restrict__ Kd, float* __restrict__ V)
{
    int gid = blockIdx.x * blockDim.x + threadIdx.x;
    int d = gid & 127;
    int t = (gid >> 7) & 511;
    int h = (gid >> 16) & 15;
    int b = gid >> 20;

    size_t base = ((size_t)(b * SEQ_ + t)) * QKVN_ + h * HD_;
    size_t oidx = ((size_t)((b * NH_ + h) * SEQ_ + t)) * HD_ + d;

    // V: passthrough
    V[oidx] = qkv[base + 2 * DIM_ + d];

    float qv, kv;
    if (d < 16) {
        int i = (d < 8) ? d : d - 8;
        // inv = 10000^{-i/8} ; ln(10000) = 9.210340371976184
        float inv = expf(-(float)i * (9.210340371976184f / 8.0f));
        float fr = (float)t * inv;
        float s, c;
        sincosf(fr, &s, &c);
        float q1 = qkv[base + i],         q2 = qkv[base + i + 8];
        float k1 = qkv[base + DIM_ + i],  k2 = qkv[base + DIM_ + i + 8];
        if (d < 8) { qv = q1 * c - q2 * s; kv = k1 * c - k2 * s; }
        else       { qv = q2 * c + q1 * s; kv = k2 * c + k1 * s; }
    } else {
        qv = qkv[base + d];
        kv = qkv[base + DIM_ + d];
    }
    Q[oidx] = qv * 0.08838834764831845f;  // 1/sqrt(128)
    Kd[oidx] = kv;
}

// ============================================================
// Flash-style causal attention.
// grid: (qt=0..3, bh=0..255). block: 256 threads.
// Each block: one (b,h), one 128-row Q tile. K/V in 64-row chunks.
// Thread pair per q row: row = tid>>1, half = tid&1 (64 out dims each).
// Output written directly in (B,T,H*hd) layout for the out-proj GEMM.
// ============================================================
#define QS_STRIDE 132
#define PS_STRIDE 65
#define ATT_SMEM_FLOATS (128*QS_STRIDE + 64*128 + 64*128 + 128*PS_STRIDE)
#define ATT_SMEM_BYTES  (ATT_SMEM_FLOATS * 4)

__global__ __launch_bounds__(256, 1) void attn_kernel(
    const float* __restrict__ Q, const float* __restrict__ K,
    const float* __restrict__ V, float* __restrict__ Y)
{
    extern __shared__ float sm[];
    float* Qs = sm;                       // [128][132]
    float* Ks = Qs + 128 * QS_STRIDE;     // [64][128]
    float* Vs = Ks + 64 * 128;            // [64][128]
    float* Ps = Vs + 64 * 128;            // [128][65]

    const int qt = blockIdx.x, bh = blockIdx.y;
    const int tid = threadIdx.x;
    const int row = tid >> 1, half = tid & 1;
    const int t = qt * 128 + row;

    const float* Qh = Q + (size_t)bh * SEQ_ * HD_;
    const float* Kh = K + (size_t)bh * SEQ_ * HD_;
    const float* Vh = V + (size_t)bh * SEQ_ * HD_;

    // load Q tile (128x128) with padded stride
    {
        const float4* src = (const float4*)(Qh + (size_t)qt * 128 * HD_);
        for (int i = tid; i < 128 * 32; i += 256) {
            int r = i >> 5, c = i & 31;
            *(float4*)(Qs + r * QS_STRIDE + c * 4) = src[i];
        }
    }

    float o[64];
#pragma unroll
    for (int j = 0; j < 64; j++) o[j] = 0.f;
    float m = -1e30f, l = 0.f;

    const int nch = 2 * qt + 2;
    for (int kc = 0; kc < nch; kc++) {
        __syncthreads();
        {
            const float4* ksrc = (const float4*)(Kh + (size_t)kc * 64 * HD_);
            const float4* vsrc = (const float4*)(Vh + (size_t)kc * 64 * HD_);
#pragma unroll
            for (int i = 0; i < 8; i++) {
                ((float4*)Ks)[tid + i * 256] = ksrc[tid + i * 256];
                ((float4*)Vs)[tid + i * 256] = vsrc[tid + i * 256];
            }
        }
        __syncthreads();

        const bool active = (kc * 64 <= t);
        if (active) {
            float s[64];
#pragma unroll
            for (int k = 0; k < 64; k++) s[k] = 0.f;

            for (int dsub = 0; dsub < 8; dsub++) {   // rolled: code-size control
                const float* qp = Qs + row * QS_STRIDE + dsub * 16;
                float4 q0 = *(const float4*)(qp + 0);
                float4 q1 = *(const float4*)(qp + 4);
                float4 q2 = *(const float4*)(qp + 8);
                float4 q3 = *(const float4*)(qp + 12);
#pragma unroll
                for (int k = 0; k < 64; k++) {
                    const float4* kp = (const float4*)(Ks + k * 128 + dsub * 16);
                    float4 k0 = kp[0], k1 = kp[1], k2 = kp[2], k3 = kp[3];
                    s[k] += q0.x*k0.x + q0.y*k0.y + q0.z*k0.z + q0.w*k0.w
                          + q1.x*k1.x + q1.y*k1.y + q1.z*k1.z + q1.w*k1.w
                          + q2.x*k2.x + q2.y*k2.y + q2.z*k2.z + q2.w*k2.w
                          + q3.x*k3.x + q3.y*k3.y + q3.z*k3.z + q3.w*k3.w;
                }
            }

            const int kbase = kc * 64;
#pragma unroll
            for (int k = 0; k < 64; k++)
                if (kbase + k > t) s[k] = -1e30f;

            float mc = -1e30f;
#pragma unroll
            for (int k = 0; k < 64; k++) mc = fmaxf(mc, s[k]);
            float mn = fmaxf(m, mc);
            float corr = __expf(m - mn);
            l *= corr;
#pragma unroll
            for (int j = 0; j < 64; j++) o[j] *= corr;
            float ls = 0.f;
#pragma unroll
            for (int k = 0; k < 64; k++) { s[k] = __expf(s[k] - mn); ls += s[k]; }
            l += ls;
            m = mn;
            // store this thread's half of p for the rolled PV loop
#pragma unroll
            for (int kk = 0; kk < 32; kk++)
                Ps[row * PS_STRIDE + half * 32 + kk] = s[half * 32 + kk];
        }
        __syncthreads();

        if (active) {
            for (int k = 0; k < 64; k++) {   // rolled k
                float p = Ps[row * PS_STRIDE + k];
                const float4* vp = (const float4*)(Vs + k * 128 + half * 64);
#pragma unroll
                for (int j4 = 0; j4 < 16; j4++) {
                    float4 v4 = vp[j4];
                    o[j4 * 4 + 0] += p * v4.x;
                    o[j4 * 4 + 1] += p * v4.y;
                    o[j4 * 4 + 2] += p * v4.z;
                    o[j4 * 4 + 3] += p * v4.w;
                }
            }
        }
    }

    const float inv_l = 1.f / l;
    const int b = bh >> 4, h = bh & 15;
    float* yp = Y + ((size_t)(b * SEQ_ + t)) * DIM_ + h * HD_ + half * 64;
#pragma unroll
    for (int j4 = 0; j4 < 16; j4++) {
        float4 v = make_float4(o[j4 * 4 + 0] * inv_l, o[j4 * 4 + 1] * inv_l,
                               o[j4 * 4 + 2] * inv_l, o[j4 * 4 + 3] * inv_l);
        *(float4*)(yp + j4 * 4) = v;
    }
}

// ============================================================
// launch
// ============================================================
extern "C" void kernel_launch(void* const* d_in, const int* in_sizes, int n_in,
                              void* d_out, int out_size)
{
    const float* x    = (const float*)d_in[0];
    const float* Wqkv = (const float*)d_in[1];
    const float* Wout = (const float*)d_in[2];
    float* out = (float*)d_out;

    float *qkv, *Q, *K, *V, *Y;
    cudaGetSymbolAddress((void**)&qkv, g_qkv);
    cudaGetSymbolAddress((void**)&Q, g_q);
    cudaGetSymbolAddress((void**)&K, g_k);
    cudaGetSymbolAddress((void**)&V, g_v);
    cudaGetSymbolAddress((void**)&Y, g_y);

    // 1) qkv = x @ Wqkv   (8192 x 6144 x 2048)
    sgemm_kernel<<<dim3(QKVN_ / 128, ROWS_ / 128), 256>>>(x, Wqkv, qkv, ROWS_, QKVN_, DIM_);

    // 2) split + rope + transpose (+ fold softmax scale into Q)
    rope_split_kernel<<<(BATCH_ * NH_ * SEQ_ * HD_) / 256, 256>>>(qkv, Q, K, V);

    // 3) causal attention -> Y in (B,T,C)
    cudaFuncSetAttribute(attn_kernel, cudaFuncAttributeMaxDynamicSharedMemorySize, ATT_SMEM_BYTES);
    attn_kernel<<<dim3(SEQ_ / 128, BATCH_ * NH_), 256, ATT_SMEM_BYTES>>>(Q, K, V, Y);

    // 4) out = Y @ Wout   (8192 x 2048 x 2048)
    sgemm_kernel<<<dim3(DIM_ / 128, ROWS_ / 128), 256>>>(Y, Wout, out, ROWS_, DIM_, DIM_);
}

// round 5
// speedup vs baseline: 1.5648x; 1.5648x over previous
#include <cuda_runtime.h>
#include <math.h>
#include <cstdint>

#define BATCH_ 16
#define SEQ_ 512
#define DIM_ 2048
#define NH_ 16
#define HD_ 128
#define ROWS_ (BATCH_*SEQ_)    // 8192
#define QKVN_ (3*DIM_)         // 6144

// ---- scratch (static device globals; no runtime allocation) ----
__device__ float g_qkv[(size_t)ROWS_ * QKVN_];
__device__ float g_q[(size_t)BATCH_*NH_*SEQ_*HD_];
__device__ float g_k[(size_t)BATCH_*NH_*SEQ_*HD_];
__device__ float g_v[(size_t)BATCH_*NH_*SEQ_*HD_];
__device__ float g_y[(size_t)ROWS_ * DIM_];

extern __shared__ char dyn_smem[];

// ============================================================
// tf32 helpers (portable mma.sync path; works on plain sm_103)
// ============================================================
__device__ __forceinline__ uint32_t f2tf32(float f) {
    uint32_t r;
    asm("cvt.rna.tf32.f32 %0, %1;" : "=r"(r) : "f"(f));
    return r;
}

// D(16x8) += A(16x8,tf32) * B(8x8,tf32)
__device__ __forceinline__ void mma_tf32(float* c, const uint32_t* a, const uint32_t* b) {
    asm volatile(
        "mma.sync.aligned.m16n8k8.row.col.f32.tf32.tf32.f32 "
        "{%0,%1,%2,%3}, {%4,%5,%6,%7}, {%8,%9}, {%0,%1,%2,%3};"
        : "+f"(c[0]), "+f"(c[1]), "+f"(c[2]), "+f"(c[3])
        : "r"(a[0]), "r"(a[1]), "r"(a[2]), "r"(a[3]), "r"(b[0]), "r"(b[1]));
}

// ============================================================
// TF32 tensor-core GEMM: C[M,N] = A[M,K] @ B[K,N], row-major fp32.
// grid (N/128, M/128), 256 threads (8 warps, 2x4).
// Block tile 128x128, BK=32, double-buffered SMEM.
// SMEM layout: As[buf][k][m] stride 136, Bs[buf][k][n] stride 136.
// ============================================================
#define KSTRIDE 136
#define CHUNK_U32 (32 * KSTRIDE)                    // per buffer per array
#define GEMM_SMEM_BYTES (4 * CHUNK_U32 * 4)         // 2 arrays x 2 buffers

__global__ __launch_bounds__(256) void tf32_gemm_kernel(
    const float* __restrict__ A, const float* __restrict__ B,
    float* __restrict__ C, int M, int N, int K)
{
    uint32_t* smu = (uint32_t*)dyn_smem;
    uint32_t* Asm = smu;                    // [2][32][136]
    uint32_t* Bsm = smu + 2 * CHUNK_U32;    // [2][32][136]

    const int tid = threadIdx.x;
    const int lane = tid & 31;
    const int w = tid >> 5;
    const int wm = (w & 1) * 64;           // warp row offset
    const int wn = (w >> 1) * 32;          // warp col offset
    const int grp = lane >> 2;             // 0..7
    const int qid = lane & 3;              // 0..3

    const int bm = blockIdx.y, bn = blockIdx.x;
    const float* Ab = A + (size_t)bm * 128 * K;
    const float* Bb = B + (size_t)bn * 128;

    const int a_r  = tid & 127;
    const int a_k4base = (tid >> 7);       // 0 or 1; full k4 = a_k4base + i*2
    const int b_c4 = tid & 31;
    const int b_krbase = tid >> 5;         // 0..7; full kr = b_krbase + i*8

    float4 ra[4], rb[4];

    auto ldg_chunk = [&](int ch) {
#pragma unroll
        for (int i = 0; i < 4; i++) {
            int k4 = a_k4base + i * 2;
            ra[i] = *(const float4*)(Ab + (size_t)a_r * K + ch * 32 + k4 * 4);
        }
#pragma unroll
        for (int i = 0; i < 4; i++) {
            int kr = b_krbase + i * 8;
            rb[i] = *(const float4*)(Bb + (size_t)(ch * 32 + kr) * N + b_c4 * 4);
        }
    };

    auto sts_chunk = [&](int buf) {
        uint32_t* As = Asm + buf * CHUNK_U32;
        uint32_t* Bs = Bsm + buf * CHUNK_U32;
#pragma unroll
        for (int i = 0; i < 4; i++) {
            int k4 = a_k4base + i * 2;
            As[(k4 * 4 + 0) * KSTRIDE + a_r] = f2tf32(ra[i].x);
            As[(k4 * 4 + 1) * KSTRIDE + a_r] = f2tf32(ra[i].y);
            As[(k4 * 4 + 2) * KSTRIDE + a_r] = f2tf32(ra[i].z);
            As[(k4 * 4 + 3) * KSTRIDE + a_r] = f2tf32(ra[i].w);
        }
#pragma unroll
        for (int i = 0; i < 4; i++) {
            int kr = b_krbase + i * 8;
            uint4 v;
            v.x = f2tf32(rb[i].x); v.y = f2tf32(rb[i].y);
            v.z = f2tf32(rb[i].z); v.w = f2tf32(rb[i].w);
            *(uint4*)&Bs[kr * KSTRIDE + b_c4 * 4] = v;
        }
    };

    float c[4][4][4];
#pragma unroll
    for (int i = 0; i < 4; i++)
#pragma unroll
        for (int j = 0; j < 4; j++)
#pragma unroll
            for (int q = 0; q < 4; q++) c[i][j][q] = 0.f;

    const int nch = K / 32;

    // prologue
    ldg_chunk(0);
    sts_chunk(0);
    __syncthreads();

    for (int ch = 0; ch < nch; ch++) {
        const int buf = ch & 1;
        if (ch + 1 < nch) ldg_chunk(ch + 1);

        const uint32_t* As = Asm + buf * CHUNK_U32;
        const uint32_t* Bs = Bsm + buf * CHUNK_U32;
#pragma unroll
        for (int ks = 0; ks < 4; ks++) {
            const int kk = ks * 8;
            uint32_t af[4][4], bf[4][2];
#pragma unroll
            for (int i = 0; i < 4; i++) {
                int m = wm + i * 16 + grp;
                af[i][0] = As[(kk + qid) * KSTRIDE + m];
                af[i][1] = As[(kk + qid) * KSTRIDE + m + 8];
                af[i][2] = As[(kk + qid + 4) * KSTRIDE + m];
                af[i][3] = As[(kk + qid + 4) * KSTRIDE + m + 8];
            }
#pragma unroll
            for (int j = 0; j < 4; j++) {
                int n = wn + j * 8 + grp;
                bf[j][0] = Bs[(kk + qid) * KSTRIDE + n];
                bf[j][1] = Bs[(kk + qid + 4) * KSTRIDE + n];
            }
#pragma unroll
            for (int i = 0; i < 4; i++)
#pragma unroll
                for (int j = 0; j < 4; j++)
                    mma_tf32(c[i][j], af[i], bf[j]);
        }

        if (ch + 1 < nch) {
            sts_chunk(buf ^ 1);
            __syncthreads();
        }
    }

    // epilogue
#pragma unroll
    for (int i = 0; i < 4; i++) {
        const int row = bm * 128 + wm + i * 16 + grp;
#pragma unroll
        for (int j = 0; j < 4; j++) {
            const int col = bn * 128 + wn + j * 8 + qid * 2;
            *(float2*)(C + (size_t)row * N + col)       = make_float2(c[i][j][0], c[i][j][1]);
            *(float2*)(C + (size_t)(row + 8) * N + col) = make_float2(c[i][j][2], c[i][j][3]);
        }
    }
}

// ============================================================
// RoPE + split qkv -> Q,K,V in [B,H,T,hd] layout (Q pre-scaled).
// ============================================================
__global__ __launch_bounds__(256) void rope_split_kernel(
    const float* __restrict__ qkv,
    float* __restrict__ Q, float* __restrict__ Kd, float* __restrict__ V)
{
    int gid = blockIdx.x * blockDim.x + threadIdx.x;
    int d = gid & 127;
    int t = (gid >> 7) & 511;
    int h = (gid >> 16) & 15;
    int b = gid >> 20;

    size_t base = ((size_t)(b * SEQ_ + t)) * QKVN_ + h * HD_;
    size_t oidx = ((size_t)((b * NH_ + h) * SEQ_ + t)) * HD_ + d;

    V[oidx] = qkv[base + 2 * DIM_ + d];

    float qv, kv;
    if (d < 16) {
        int i = (d < 8) ? d : d - 8;
        float inv = expf(-(float)i * (9.210340371976184f / 8.0f));
        float fr = (float)t * inv;
        float s, c;
        sincosf(fr, &s, &c);
        float q1 = qkv[base + i],         q2 = qkv[base + i + 8];
        float k1 = qkv[base + DIM_ + i],  k2 = qkv[base + DIM_ + i + 8];
        if (d < 8) { qv = q1 * c - q2 * s; kv = k1 * c - k2 * s; }
        else       { qv = q2 * c + q1 * s; kv = k2 * c + k1 * s; }
    } else {
        qv = qkv[base + d];
        kv = qkv[base + DIM_ + d];
    }
    Q[oidx] = qv * 0.08838834764831845f;
    Kd[oidx] = kv;
}

// ============================================================
// Flash-style causal attention (fp32). grid (4, 256), 256 thr.
// ============================================================
#define QS_STRIDE 132
#define PS_STRIDE 65
#define ATT_SMEM_FLOATS (128*QS_STRIDE + 64*128 + 64*128 + 128*PS_STRIDE)
#define ATT_SMEM_BYTES  (ATT_SMEM_FLOATS * 4)

__global__ __launch_bounds__(256, 1) void attn_kernel(
    const float* __restrict__ Q, const float* __restrict__ K,
    const float* __restrict__ V, float* __restrict__ Y)
{
    float* smf = (float*)dyn_smem;
    float* Qs = smf;
    float* Ks = Qs + 128 * QS_STRIDE;
    float* Vs = Ks + 64 * 128;
    float* Ps = Vs + 64 * 128;

    const int qt = blockIdx.x, bh = blockIdx.y;
    const int tid = threadIdx.x;
    const int row = tid >> 1, half = tid & 1;
    const int t = qt * 128 + row;

    const float* Qh = Q + (size_t)bh * SEQ_ * HD_;
    const float* Kh = K + (size_t)bh * SEQ_ * HD_;
    const float* Vh = V + (size_t)bh * SEQ_ * HD_;

    {
        const float4* src = (const float4*)(Qh + (size_t)qt * 128 * HD_);
        for (int i = tid; i < 128 * 32; i += 256) {
            int r = i >> 5, c = i & 31;
            *(float4*)(Qs + r * QS_STRIDE + c * 4) = src[i];
        }
    }

    float o[64];
#pragma unroll
    for (int j = 0; j < 64; j++) o[j] = 0.f;
    float m = -1e30f, l = 0.f;

    const int nch = 2 * qt + 2;
    for (int kc = 0; kc < nch; kc++) {
        __syncthreads();
        {
            const float4* ksrc = (const float4*)(Kh + (size_t)kc * 64 * HD_);
            const float4* vsrc = (const float4*)(Vh + (size_t)kc * 64 * HD_);
#pragma unroll
            for (int i = 0; i < 8; i++) {
                ((float4*)Ks)[tid + i * 256] = ksrc[tid + i * 256];
                ((float4*)Vs)[tid + i * 256] = vsrc[tid + i * 256];
            }
        }
        __syncthreads();

        const bool active = (kc * 64 <= t);
        if (active) {
            float s[64];
#pragma unroll
            for (int k = 0; k < 64; k++) s[k] = 0.f;

            for (int dsub = 0; dsub < 8; dsub++) {
                const float* qp = Qs + row * QS_STRIDE + dsub * 16;
                float4 q0 = *(const float4*)(qp + 0);
                float4 q1 = *(const float4*)(qp + 4);
                float4 q2 = *(const float4*)(qp + 8);
                float4 q3 = *(const float4*)(qp + 12);
#pragma unroll
                for (int k = 0; k < 64; k++) {
                    const float4* kp = (const float4*)(Ks + k * 128 + dsub * 16);
                    float4 k0 = kp[0], k1 = kp[1], k2 = kp[2], k3 = kp[3];
                    s[k] += q0.x*k0.x + q0.y*k0.y + q0.z*k0.z + q0.w*k0.w
                          + q1.x*k1.x + q1.y*k1.y + q1.z*k1.z + q1.w*k1.w
                          + q2.x*k2.x + q2.y*k2.y + q2.z*k2.z + q2.w*k2.w
                          + q3.x*k3.x + q3.y*k3.y + q3.z*k3.z + q3.w*k3.w;
                }
            }

            const int kbase = kc * 64;
#pragma unroll
            for (int k = 0; k < 64; k++)
                if (kbase + k > t) s[k] = -1e30f;

            float mc = -1e30f;
#pragma unroll
            for (int k = 0; k < 64; k++) mc = fmaxf(mc, s[k]);
            float mn = fmaxf(m, mc);
            float corr = __expf(m - mn);
            l *= corr;
#pragma unroll
            for (int j = 0; j < 64; j++) o[j] *= corr;
            float ls = 0.f;
#pragma unroll
            for (int k = 0; k < 64; k++) { s[k] = __expf(s[k] - mn); ls += s[k]; }
            l += ls;
            m = mn;
#pragma unroll
            for (int kk = 0; kk < 32; kk++)
                Ps[row * PS_STRIDE + half * 32 + kk] = s[half * 32 + kk];
        }
        __syncthreads();

        if (active) {
            for (int k = 0; k < 64; k++) {
                float p = Ps[row * PS_STRIDE + k];
                const float4* vp = (const float4*)(Vs + k * 128 + half * 64);
#pragma unroll
                for (int j4 = 0; j4 < 16; j4++) {
                    float4 v4 = vp[j4];
                    o[j4 * 4 + 0] += p * v4.x;
                    o[j4 * 4 + 1] += p * v4.y;
                    o[j4 * 4 + 2] += p * v4.z;
                    o[j4 * 4 + 3] += p * v4.w;
                }
            }
        }
    }

    const float inv_l = 1.f / l;
    const int b = bh >> 4, h = bh & 15;
    float* yp = Y + ((size_t)(b * SEQ_ + t)) * DIM_ + h * HD_ + half * 64;
#pragma unroll
    for (int j4 = 0; j4 < 16; j4++) {
        float4 v = make_float4(o[j4 * 4 + 0] * inv_l, o[j4 * 4 + 1] * inv_l,
                               o[j4 * 4 + 2] * inv_l, o[j4 * 4 + 3] * inv_l);
        *(float4*)(yp + j4 * 4) = v;
    }
}

// ============================================================
// launch
// ============================================================
extern "C" void kernel_launch(void* const* d_in, const int* in_sizes, int n_in,
                              void* d_out, int out_size)
{
    const float* x    = (const float*)d_in[0];
    const float* Wqkv = (const float*)d_in[1];
    const float* Wout = (const float*)d_in[2];
    float* out = (float*)d_out;

    float *qkv, *Q, *K, *V, *Y;
    cudaGetSymbolAddress((void**)&qkv, g_qkv);
    cudaGetSymbolAddress((void**)&Q, g_q);
    cudaGetSymbolAddress((void**)&K, g_k);
    cudaGetSymbolAddress((void**)&V, g_v);
    cudaGetSymbolAddress((void**)&Y, g_y);

    cudaFuncSetAttribute(tf32_gemm_kernel, cudaFuncAttributeMaxDynamicSharedMemorySize, GEMM_SMEM_BYTES);
    cudaFuncSetAttribute(attn_kernel, cudaFuncAttributeMaxDynamicSharedMemorySize, ATT_SMEM_BYTES);

    // 1) qkv = x @ Wqkv   (8192 x 6144 x 2048), tf32 mma.sync tensor cores
    tf32_gemm_kernel<<<dim3(QKVN_ / 128, ROWS_ / 128), 256, GEMM_SMEM_BYTES>>>(x, Wqkv, qkv, ROWS_, QKVN_, DIM_);

    // 2) split + rope + transpose (+ fold softmax scale into Q)
    rope_split_kernel<<<(BATCH_ * NH_ * SEQ_ * HD_) / 256, 256>>>(qkv, Q, K, V);

    // 3) causal attention -> Y in (B,T,C)
    attn_kernel<<<dim3(SEQ_ / 128, BATCH_ * NH_), 256, ATT_SMEM_BYTES>>>(Q, K, V, Y);

    // 4) out = Y @ Wout   (8192 x 2048 x 2048), tf32 mma.sync tensor cores
    tf32_gemm_kernel<<<dim3(DIM_ / 128, ROWS_ / 128), 256, GEMM_SMEM_BYTES>>>(Y, Wout, out, ROWS_, DIM_, DIM_);
}

// round 6
// speedup vs baseline: 2.1286x; 1.3603x over previous
#include <cuda_runtime.h>
#include <math.h>
#include <cstdint>

#define BATCH_ 16
#define SEQ_ 512
#define DIM_ 2048
#define NH_ 16
#define HD_ 128
#define ROWS_ (BATCH_*SEQ_)    // 8192
#define QKVN_ (3*DIM_)         // 6144

// ---- scratch (static device globals; no runtime allocation) ----
__device__ float g_qkv[(size_t)ROWS_ * QKVN_];
__device__ float g_q[(size_t)BATCH_*NH_*SEQ_*HD_];
__device__ float g_k[(size_t)BATCH_*NH_*SEQ_*HD_];
__device__ float g_v[(size_t)BATCH_*NH_*SEQ_*HD_];
__device__ float g_y[(size_t)ROWS_ * DIM_];

extern __shared__ char dyn_smem[];

// ============================================================
// tf32 helpers (portable mma.sync path; works on plain sm_103)
// ============================================================
__device__ __forceinline__ uint32_t f2tf32(float f) {
    uint32_t r;
    asm("cvt.rna.tf32.f32 %0, %1;" : "=r"(r) : "f"(f));
    return r;
}

// D(16x8) += A(16x8,tf32) * B(8x8,tf32)
__device__ __forceinline__ void mma_tf32(float* c, const uint32_t* a, const uint32_t* b) {
    asm volatile(
        "mma.sync.aligned.m16n8k8.row.col.f32.tf32.tf32.f32 "
        "{%0,%1,%2,%3}, {%4,%5,%6,%7}, {%8,%9}, {%0,%1,%2,%3};"
        : "+f"(c[0]), "+f"(c[1]), "+f"(c[2]), "+f"(c[3])
        : "r"(a[0]), "r"(a[1]), "r"(a[2]), "r"(a[3]), "r"(b[0]), "r"(b[1]));
}

// ============================================================
// TF32 tensor-core GEMM: C[M,N] = A[M,K] @ B[K,N], row-major fp32.
// (unchanged from round 5 — passing at ~258 TF/s)
// ============================================================
#define KSTRIDE 136
#define CHUNK_U32 (32 * KSTRIDE)
#define GEMM_SMEM_BYTES (4 * CHUNK_U32 * 4)

__global__ __launch_bounds__(256) void tf32_gemm_kernel(
    const float* __restrict__ A, const float* __restrict__ B,
    float* __restrict__ C, int M, int N, int K)
{
    uint32_t* smu = (uint32_t*)dyn_smem;
    uint32_t* Asm = smu;
    uint32_t* Bsm = smu + 2 * CHUNK_U32;

    const int tid = threadIdx.x;
    const int lane = tid & 31;
    const int w = tid >> 5;
    const int wm = (w & 1) * 64;
    const int wn = (w >> 1) * 32;
    const int grp = lane >> 2;
    const int qid = lane & 3;

    const int bm = blockIdx.y, bn = blockIdx.x;
    const float* Ab = A + (size_t)bm * 128 * K;
    const float* Bb = B + (size_t)bn * 128;

    const int a_r  = tid & 127;
    const int a_k4base = (tid >> 7);
    const int b_c4 = tid & 31;
    const int b_krbase = tid >> 5;

    float4 ra[4], rb[4];

    auto ldg_chunk = [&](int ch) {
#pragma unroll
        for (int i = 0; i < 4; i++) {
            int k4 = a_k4base + i * 2;
            ra[i] = *(const float4*)(Ab + (size_t)a_r * K + ch * 32 + k4 * 4);
        }
#pragma unroll
        for (int i = 0; i < 4; i++) {
            int kr = b_krbase + i * 8;
            rb[i] = *(const float4*)(Bb + (size_t)(ch * 32 + kr) * N + b_c4 * 4);
        }
    };

    auto sts_chunk = [&](int buf) {
        uint32_t* As = Asm + buf * CHUNK_U32;
        uint32_t* Bs = Bsm + buf * CHUNK_U32;
#pragma unroll
        for (int i = 0; i < 4; i++) {
            int k4 = a_k4base + i * 2;
            As[(k4 * 4 + 0) * KSTRIDE + a_r] = f2tf32(ra[i].x);
            As[(k4 * 4 + 1) * KSTRIDE + a_r] = f2tf32(ra[i].y);
            As[(k4 * 4 + 2) * KSTRIDE + a_r] = f2tf32(ra[i].z);
            As[(k4 * 4 + 3) * KSTRIDE + a_r] = f2tf32(ra[i].w);
        }
#pragma unroll
        for (int i = 0; i < 4; i++) {
            int kr = b_krbase + i * 8;
            uint4 v;
            v.x = f2tf32(rb[i].x); v.y = f2tf32(rb[i].y);
            v.z = f2tf32(rb[i].z); v.w = f2tf32(rb[i].w);
            *(uint4*)&Bs[kr * KSTRIDE + b_c4 * 4] = v;
        }
    };

    float c[4][4][4];
#pragma unroll
    for (int i = 0; i < 4; i++)
#pragma unroll
        for (int j = 0; j < 4; j++)
#pragma unroll
            for (int q = 0; q < 4; q++) c[i][j][q] = 0.f;

    const int nch = K / 32;

    ldg_chunk(0);
    sts_chunk(0);
    __syncthreads();

    for (int ch = 0; ch < nch; ch++) {
        const int buf = ch & 1;
        if (ch + 1 < nch) ldg_chunk(ch + 1);

        const uint32_t* As = Asm + buf * CHUNK_U32;
        const uint32_t* Bs = Bsm + buf * CHUNK_U32;
#pragma unroll
        for (int ks = 0; ks < 4; ks++) {
            const int kk = ks * 8;
            uint32_t af[4][4], bf[4][2];
#pragma unroll
            for (int i = 0; i < 4; i++) {
                int m = wm + i * 16 + grp;
                af[i][0] = As[(kk + qid) * KSTRIDE + m];
                af[i][1] = As[(kk + qid) * KSTRIDE + m + 8];
                af[i][2] = As[(kk + qid + 4) * KSTRIDE + m];
                af[i][3] = As[(kk + qid + 4) * KSTRIDE + m + 8];
            }
#pragma unroll
            for (int j = 0; j < 4; j++) {
                int n = wn + j * 8 + grp;
                bf[j][0] = Bs[(kk + qid) * KSTRIDE + n];
                bf[j][1] = Bs[(kk + qid + 4) * KSTRIDE + n];
            }
#pragma unroll
            for (int i = 0; i < 4; i++)
#pragma unroll
                for (int j = 0; j < 4; j++)
                    mma_tf32(c[i][j], af[i], bf[j]);
        }

        if (ch + 1 < nch) {
            sts_chunk(buf ^ 1);
            __syncthreads();
        }
    }

#pragma unroll
    for (int i = 0; i < 4; i++) {
        const int row = bm * 128 + wm + i * 16 + grp;
#pragma unroll
        for (int j = 0; j < 4; j++) {
            const int col = bn * 128 + wn + j * 8 + qid * 2;
            *(float2*)(C + (size_t)row * N + col)       = make_float2(c[i][j][0], c[i][j][1]);
            *(float2*)(C + (size_t)(row + 8) * N + col) = make_float2(c[i][j][2], c[i][j][3]);
        }
    }
}

// ============================================================
// RoPE + split qkv -> Q,K,V in [B,H,T,hd] layout (Q pre-scaled).
// ============================================================
__global__ __launch_bounds__(256) void rope_split_kernel(
    const float* __restrict__ qkv,
    float* __restrict__ Q, float* __restrict__ Kd, float* __restrict__ V)
{
    int gid = blockIdx.x * blockDim.x + threadIdx.x;
    int d = gid & 127;
    int t = (gid >> 7) & 511;
    int h = (gid >> 16) & 15;
    int b = gid >> 20;

    size_t base = ((size_t)(b * SEQ_ + t)) * QKVN_ + h * HD_;
    size_t oidx = ((size_t)((b * NH_ + h) * SEQ_ + t)) * HD_ + d;

    V[oidx] = qkv[base + 2 * DIM_ + d];

    float qv, kv;
    if (d < 16) {
        int i = (d < 8) ? d : d - 8;
        float inv = expf(-(float)i * (9.210340371976184f / 8.0f));
        float fr = (float)t * inv;
        float s, c;
        sincosf(fr, &s, &c);
        float q1 = qkv[base + i],         q2 = qkv[base + i + 8];
        float k1 = qkv[base + DIM_ + i],  k2 = qkv[base + DIM_ + i + 8];
        if (d < 8) { qv = q1 * c - q2 * s; kv = k1 * c - k2 * s; }
        else       { qv = q2 * c + q1 * s; kv = k2 * c + k1 * s; }
    } else {
        qv = qkv[base + d];
        kv = qkv[base + DIM_ + d];
    }
    Q[oidx] = qv * 0.08838834764831845f;
    Kd[oidx] = kv;
}

// ============================================================
// Tensor-core flash attention (tf32 mma.sync), causal.
// grid (4, 256), 256 threads (8 warps).
// Block: one (b,h), one 128-row Q tile. K/V chunks of 64.
// Warp w owns q-rows [w*16, w*16+16). Per chunk:
//   S(16x64) = Q_w(16x128) @ K^T   (128 MMAs)
//   online softmax on fragments (shfl over qid lanes)
//   P -> per-warp SMEM (tf32) -> A-fragments
//   O(16x128) += P @ V            (128 MMAs)
// SMEM strides: Qs/Ks 140, Vs 136, Ps 76 — conflict-free for the
// fragment patterns (banks grp*12+qid / qid*8+grp, all distinct).
// ============================================================
#define AQ_STRIDE 140
#define AK_STRIDE 140
#define AV_STRIDE 136
#define AP_STRIDE 76
#define AQ_U32 (128 * AQ_STRIDE)
#define AK_U32 (64 * AK_STRIDE)
#define AV_U32 (64 * AV_STRIDE)
#define AP_U32 (8 * 16 * AP_STRIDE)
#define ATT_SMEM_BYTES ((AQ_U32 + AK_U32 + AV_U32 + AP_U32) * 4)

__global__ __launch_bounds__(256, 1) void attn_mma_kernel(
    const float* __restrict__ Q, const float* __restrict__ K,
    const float* __restrict__ V, float* __restrict__ Y)
{
    uint32_t* smu = (uint32_t*)dyn_smem;
    uint32_t* Qs = smu;
    uint32_t* Ks = Qs + AQ_U32;
    uint32_t* Vs = Ks + AK_U32;
    uint32_t* Ps = Vs + AV_U32;

    const int qt = blockIdx.x, bh = blockIdx.y;
    const int tid = threadIdx.x;
    const int lane = tid & 31;
    const int w = tid >> 5;
    const int grp = lane >> 2;   // 0..7
    const int qid = lane & 3;    // 0..3

    const float* Qh = Q + (size_t)bh * SEQ_ * HD_;
    const float* Kh = K + (size_t)bh * SEQ_ * HD_;
    const float* Vh = V + (size_t)bh * SEQ_ * HD_;

    // ---- load Q tile (128x128) as tf32 ----
    {
        const float4* src = (const float4*)(Qh + (size_t)qt * 128 * HD_);
#pragma unroll
        for (int i = 0; i < 16; i++) {
            int idx = tid + i * 256;            // 0..4095
            int r = idx >> 5, c4 = idx & 31;
            float4 v = src[idx];
            uint32_t* dst = Qs + r * AQ_STRIDE + c4 * 4;
            dst[0] = f2tf32(v.x); dst[1] = f2tf32(v.y);
            dst[2] = f2tf32(v.z); dst[3] = f2tf32(v.w);
        }
    }

    uint32_t* Pw = Ps + w * 16 * AP_STRIDE;     // this warp's private P tile

    float o[16][4];
#pragma unroll
    for (int j = 0; j < 16; j++)
#pragma unroll
        for (int q = 0; q < 4; q++) o[j][q] = 0.f;
    float m0 = -1e30f, m1 = -1e30f, l0 = 0.f, l1 = 0.f;

    const int r0g = qt * 128 + w * 16 + grp;    // global q row (half 0)
    const int r1g = r0g + 8;                    // global q row (half 1)

    const int nch = 2 * qt + 2;
    for (int kc = 0; kc < nch; kc++) {
        __syncthreads();   // all warps done reading previous K/V
        // ---- load K,V chunk (64x128 each) as tf32 ----
        {
            const float4* ksrc = (const float4*)(Kh + (size_t)kc * 64 * HD_);
            const float4* vsrc = (const float4*)(Vh + (size_t)kc * 64 * HD_);
#pragma unroll
            for (int i = 0; i < 8; i++) {
                int idx = tid + i * 256;        // 0..2047
                int r = idx >> 5, c4 = idx & 31;
                float4 kv4 = ksrc[idx];
                uint32_t* kd = Ks + r * AK_STRIDE + c4 * 4;
                kd[0] = f2tf32(kv4.x); kd[1] = f2tf32(kv4.y);
                kd[2] = f2tf32(kv4.z); kd[3] = f2tf32(kv4.w);
                float4 vv4 = vsrc[idx];
                uint32_t* vd = Vs + r * AV_STRIDE + c4 * 4;
                vd[0] = f2tf32(vv4.x); vd[1] = f2tf32(vv4.y);
                vd[2] = f2tf32(vv4.z); vd[3] = f2tf32(vv4.w);
            }
        }
        __syncthreads();

        // ---- S = Q_w @ K^T : s[8 n-tiles][4] ----
        float s[8][4];
#pragma unroll
        for (int j = 0; j < 8; j++)
#pragma unroll
            for (int q = 0; q < 4; q++) s[j][q] = 0.f;

#pragma unroll
        for (int kk = 0; kk < 16; kk++) {
            uint32_t a[4];
            const uint32_t* qb = Qs + (w * 16 + grp) * AQ_STRIDE + kk * 8;
            a[0] = qb[qid];
            a[1] = qb[8 * AQ_STRIDE + qid];
            a[2] = qb[qid + 4];
            a[3] = qb[8 * AQ_STRIDE + qid + 4];
#pragma unroll
            for (int j = 0; j < 8; j++) {
                uint32_t b[2];
                const uint32_t* kb = Ks + (j * 8 + grp) * AK_STRIDE + kk * 8;
                b[0] = kb[qid];
                b[1] = kb[qid + 4];
                mma_tf32(s[j], a, b);
            }
        }

        // ---- causal mask ----
        const int cbase = kc * 64;
#pragma unroll
        for (int j = 0; j < 8; j++) {
            const int c0 = cbase + j * 8 + 2 * qid;
            if (c0 > r0g)     s[j][0] = -1e30f;
            if (c0 + 1 > r0g) s[j][1] = -1e30f;
            if (c0 > r1g)     s[j][2] = -1e30f;
            if (c0 + 1 > r1g) s[j][3] = -1e30f;
        }

        // ---- online softmax (rows r0g, r1g per lane) ----
        float mc0 = -1e30f, mc1 = -1e30f;
#pragma unroll
        for (int j = 0; j < 8; j++) {
            mc0 = fmaxf(mc0, fmaxf(s[j][0], s[j][1]));
            mc1 = fmaxf(mc1, fmaxf(s[j][2], s[j][3]));
        }
        mc0 = fmaxf(mc0, __shfl_xor_sync(0xFFFFFFFF, mc0, 1));
        mc0 = fmaxf(mc0, __shfl_xor_sync(0xFFFFFFFF, mc0, 2));
        mc1 = fmaxf(mc1, __shfl_xor_sync(0xFFFFFFFF, mc1, 1));
        mc1 = fmaxf(mc1, __shfl_xor_sync(0xFFFFFFFF, mc1, 2));

        const float mn0 = fmaxf(m0, mc0);
        const float mn1 = fmaxf(m1, mc1);
        const float corr0 = __expf(m0 - mn0);
        const float corr1 = __expf(m1 - mn1);
        m0 = mn0; m1 = mn1;

        float ls0 = 0.f, ls1 = 0.f;
#pragma unroll
        for (int j = 0; j < 8; j++) {
            s[j][0] = __expf(s[j][0] - mn0);
            s[j][1] = __expf(s[j][1] - mn0);
            s[j][2] = __expf(s[j][2] - mn1);
            s[j][3] = __expf(s[j][3] - mn1);
            ls0 += s[j][0] + s[j][1];
            ls1 += s[j][2] + s[j][3];
        }
        ls0 += __shfl_xor_sync(0xFFFFFFFF, ls0, 1);
        ls0 += __shfl_xor_sync(0xFFFFFFFF, ls0, 2);
        ls1 += __shfl_xor_sync(0xFFFFFFFF, ls1, 1);
        ls1 += __shfl_xor_sync(0xFFFFFFFF, ls1, 2);
        l0 = l0 * corr0 + ls0;
        l1 = l1 * corr1 + ls1;

        // rescale O
#pragma unroll
        for (int j = 0; j < 16; j++) {
            o[j][0] *= corr0; o[j][1] *= corr0;
            o[j][2] *= corr1; o[j][3] *= corr1;
        }

        // ---- P -> per-warp SMEM (tf32) ----
#pragma unroll
        for (int j = 0; j < 8; j++) {
            uint32_t* p0 = Pw + grp * AP_STRIDE + j * 8 + 2 * qid;
            p0[0] = f2tf32(s[j][0]);
            p0[1] = f2tf32(s[j][1]);
            uint32_t* p1 = p0 + 8 * AP_STRIDE;
            p1[0] = f2tf32(s[j][2]);
            p1[1] = f2tf32(s[j][3]);
        }
        __syncwarp();

        // ---- O += P @ V ----
#pragma unroll
        for (int kk = 0; kk < 8; kk++) {
            uint32_t a[4];
            const uint32_t* pb = Pw + grp * AP_STRIDE + kk * 8;
            a[0] = pb[qid];
            a[1] = pb[8 * AP_STRIDE + qid];
            a[2] = pb[qid + 4];
            a[3] = pb[8 * AP_STRIDE + qid + 4];
#pragma unroll
            for (int j = 0; j < 16; j++) {
                uint32_t b[2];
                const uint32_t* vb = Vs + (kk * 8 + qid) * AV_STRIDE + j * 8 + grp;
                b[0] = vb[0];
                b[1] = vb[4 * AV_STRIDE];
                mma_tf32(o[j], a, b);
            }
        }
        __syncwarp();   // P readers done before next chunk overwrites
    }

    // ---- write Y (B,T,C) ----
    const float inv0 = 1.f / l0;
    const float inv1 = 1.f / l1;
    const int b = bh >> 4, h = bh & 15;
    float* y0 = Y + ((size_t)(b * SEQ_ + r0g)) * DIM_ + h * HD_;
    float* y1 = Y + ((size_t)(b * SEQ_ + r1g)) * DIM_ + h * HD_;
#pragma unroll
    for (int j = 0; j < 16; j++) {
        const int col = j * 8 + 2 * qid;
        *(float2*)(y0 + col) = make_float2(o[j][0] * inv0, o[j][1] * inv0);
        *(float2*)(y1 + col) = make_float2(o[j][2] * inv1, o[j][3] * inv1);
    }
}

// ============================================================
// launch
// ============================================================
extern "C" void kernel_launch(void* const* d_in, const int* in_sizes, int n_in,
                              void* d_out, int out_size)
{
    const float* x    = (const float*)d_in[0];
    const float* Wqkv = (const float*)d_in[1];
    const float* Wout = (const float*)d_in[2];
    float* out = (float*)d_out;

    float *qkv, *Q, *K, *V, *Y;
    cudaGetSymbolAddress((void**)&qkv, g_qkv);
    cudaGetSymbolAddress((void**)&Q, g_q);
    cudaGetSymbolAddress((void**)&K, g_k);
    cudaGetSymbolAddress((void**)&V, g_v);
    cudaGetSymbolAddress((void**)&Y, g_y);

    cudaFuncSetAttribute(tf32_gemm_kernel, cudaFuncAttributeMaxDynamicSharedMemorySize, GEMM_SMEM_BYTES);
    cudaFuncSetAttribute(attn_mma_kernel, cudaFuncAttributeMaxDynamicSharedMemorySize, ATT_SMEM_BYTES);

    // 1) qkv = x @ Wqkv   (8192 x 6144 x 2048)
    tf32_gemm_kernel<<<dim3(QKVN_ / 128, ROWS_ / 128), 256, GEMM_SMEM_BYTES>>>(x, Wqkv, qkv, ROWS_, QKVN_, DIM_);

    // 2) split + rope + transpose (+ fold softmax scale into Q)
    rope_split_kernel<<<(BATCH_ * NH_ * SEQ_ * HD_) / 256, 256>>>(qkv, Q, K, V);

    // 3) causal attention -> Y in (B,T,C), tensor cores
    attn_mma_kernel<<<dim3(SEQ_ / 128, BATCH_ * NH_), 256, ATT_SMEM_BYTES>>>(Q, K, V, Y);

    // 4) out = Y @ Wout   (8192 x 2048 x 2048)
    tf32_gemm_kernel<<<dim3(DIM_ / 128, ROWS_ / 128), 256, GEMM_SMEM_BYTES>>>(Y, Wout, out, ROWS_, DIM_, DIM_);
}

// round 7
// speedup vs baseline: 4.1444x; 1.9470x over previous
#include <cuda_runtime.h>
#include <math.h>
#include <cstdint>

#define BATCH_ 16
#define SEQ_ 512
#define DIM_ 2048
#define NH_ 16
#define HD_ 128
#define ROWS_ (BATCH_*SEQ_)    // 8192
#define QKVN_ (3*DIM_)         // 6144

// ---- scratch (static device globals; no runtime allocation) ----
__device__ float g_qkv[(size_t)ROWS_ * QKVN_];
__device__ float g_q[(size_t)BATCH_*NH_*SEQ_*HD_];
__device__ float g_k[(size_t)BATCH_*NH_*SEQ_*HD_];
__device__ float g_v[(size_t)BATCH_*NH_*SEQ_*HD_];
__device__ float g_y[(size_t)ROWS_ * DIM_];
__device__ float g_xr[(size_t)ROWS_ * DIM_];       // tf32-rounded x
__device__ float g_wqkvr[(size_t)DIM_ * QKVN_];    // tf32-rounded Wqkv
__device__ float g_woutr[(size_t)DIM_ * DIM_];     // tf32-rounded Wout

extern __shared__ char dyn_smem[];

// ============================================================
// helpers
// ============================================================
__device__ __forceinline__ uint32_t f2tf32(float f) {
    uint32_t r;
    asm("cvt.rna.tf32.f32 %0, %1;" : "=r"(r) : "f"(f));
    return r;
}
__device__ __forceinline__ float tf32r(float f) { return __uint_as_float(f2tf32(f)); }

__device__ __forceinline__ void mma_tf32(float* c, const uint32_t* a, const uint32_t* b) {
    asm volatile(
        "mma.sync.aligned.m16n8k8.row.col.f32.tf32.tf32.f32 "
        "{%0,%1,%2,%3}, {%4,%5,%6,%7}, {%8,%9}, {%0,%1,%2,%3};"
        : "+f"(c[0]), "+f"(c[1]), "+f"(c[2]), "+f"(c[3])
        : "r"(a[0]), "r"(a[1]), "r"(a[2]), "r"(a[3]), "r"(b[0]), "r"(b[1]));
}

__device__ __forceinline__ uint32_t smem_u32(const void* p) {
    uint32_t a;
    asm("{ .reg .u64 t; cvta.to.shared.u64 t, %1; cvt.u32.u64 %0, t; }" : "=r"(a) : "l"(p));
    return a;
}
__device__ __forceinline__ void cp16(uint32_t dst, const void* src) {
    asm volatile("cp.async.cg.shared.global [%0], [%1], 16;" :: "r"(dst), "l"(src) : "memory");
}
#define CP_COMMIT() asm volatile("cp.async.commit_group;" ::: "memory")
#define CP_WAIT(n)  asm volatile("cp.async.wait_group %0;" :: "n"(n) : "memory")

// ============================================================
// tf32 rounding (elementwise, float4)
// ============================================================
__global__ __launch_bounds__(256) void round_tf32_kernel(
    const float4* __restrict__ in, float4* __restrict__ out, int n4)
{
    int i = blockIdx.x * blockDim.x + threadIdx.x;
    if (i < n4) {
        float4 v = in[i];
        v.x = tf32r(v.x); v.y = tf32r(v.y); v.z = tf32r(v.z); v.w = tf32r(v.w);
        out[i] = v;
    }
}

// ============================================================
// TF32 GEMM, cp.async 3-stage: C[M,N] = A[M,K] @ B[K,N].
// Inputs MUST be pre-rounded to tf32. grid (N/128, M/128), 256 thr.
// As[m][k] stride 36, Bs[k][n] stride 136 (both fragment-conflict-free).
// ============================================================
#define GA_STRIDE 36
#define GB_STRIDE 136
#define GA_U32 (128 * GA_STRIDE)      // 4608
#define GB_U32 (32 * GB_STRIDE)       // 4352
#define GSTAGE_U32 (GA_U32 + GB_U32)  // 8960
#define GEMM_SMEM_BYTES (3 * GSTAGE_U32 * 4)   // 107520

__global__ __launch_bounds__(256) void tf32_gemm_async(
    const float* __restrict__ A, const float* __restrict__ B,
    float* __restrict__ C, int M, int N, int K)
{
    const uint32_t sbase = smem_u32(dyn_smem);
    uint32_t* smu = (uint32_t*)dyn_smem;

    const int tid = threadIdx.x;
    const int lane = tid & 31;
    const int w = tid >> 5;
    const int wm = (w & 1) * 64;
    const int wn = (w >> 1) * 32;
    const int grp = lane >> 2;
    const int qid = lane & 3;

    const int bm = blockIdx.y, bn = blockIdx.x;
    const float* Ab = A + (size_t)bm * 128 * K;
    const float* Bb = B + (size_t)bn * 128;

    const int nch = K / 32;

    auto issue = [&](int ch, int s) {
        const uint32_t sa = sbase + (uint32_t)(s * GSTAGE_U32) * 4;
        const uint32_t sb = sa + GA_U32 * 4;
#pragma unroll
        for (int i = 0; i < 4; i++) {
            int cidx = tid + i * 256;          // 0..1023
            int r = cidx >> 3, c4 = cidx & 7;  // A: 128 rows x 8 chunks
            cp16(sa + (uint32_t)(r * GA_STRIDE + c4 * 4) * 4,
                 Ab + (size_t)r * K + ch * 32 + c4 * 4);
        }
#pragma unroll
        for (int i = 0; i < 4; i++) {
            int cidx = tid + i * 256;           // 0..1023
            int r = cidx >> 5, c4 = cidx & 31;  // B: 32 rows x 32 chunks
            cp16(sb + (uint32_t)(r * GB_STRIDE + c4 * 4) * 4,
                 Bb + (size_t)(ch * 32 + r) * N + c4 * 4);
        }
        CP_COMMIT();
    };

    float c[4][4][4];
#pragma unroll
    for (int i = 0; i < 4; i++)
#pragma unroll
        for (int j = 0; j < 4; j++)
#pragma unroll
            for (int q = 0; q < 4; q++) c[i][j][q] = 0.f;

    issue(0, 0);
    issue(1, 1);

    for (int ch = 0; ch < nch; ch++) {
        if (ch + 1 < nch) { CP_WAIT(1); } else { CP_WAIT(0); }
        __syncthreads();

        const uint32_t* As = smu + (ch % 3) * GSTAGE_U32;
        const uint32_t* Bs = As + GA_U32;
#pragma unroll
        for (int ks = 0; ks < 4; ks++) {
            const int kk = ks * 8;
            uint32_t af[4][4], bf[4][2];
#pragma unroll
            for (int i = 0; i < 4; i++) {
                const int m = wm + i * 16 + grp;
                af[i][0] = As[m * GA_STRIDE + kk + qid];
                af[i][1] = As[(m + 8) * GA_STRIDE + kk + qid];
                af[i][2] = As[m * GA_STRIDE + kk + qid + 4];
                af[i][3] = As[(m + 8) * GA_STRIDE + kk + qid + 4];
            }
#pragma unroll
            for (int j = 0; j < 4; j++) {
                const int n = wn + j * 8 + grp;
                bf[j][0] = Bs[(kk + qid) * GB_STRIDE + n];
                bf[j][1] = Bs[(kk + qid + 4) * GB_STRIDE + n];
            }
#pragma unroll
            for (int i = 0; i < 4; i++)
#pragma unroll
                for (int j = 0; j < 4; j++)
                    mma_tf32(c[i][j], af[i], bf[j]);
        }

        if (ch + 2 < nch) issue(ch + 2, (ch + 2) % 3);
    }

#pragma unroll
    for (int i = 0; i < 4; i++) {
        const int row = bm * 128 + wm + i * 16 + grp;
#pragma unroll
        for (int j = 0; j < 4; j++) {
            const int col = bn * 128 + wn + j * 8 + qid * 2;
            *(float2*)(C + (size_t)row * N + col)       = make_float2(c[i][j][0], c[i][j][1]);
            *(float2*)(C + (size_t)(row + 8) * N + col) = make_float2(c[i][j][2], c[i][j][3]);
        }
    }
}

// ============================================================
// RoPE + split -> Q,K,V in [B,H,T,hd], tf32-rounded, Q pre-scaled.
// ============================================================
__global__ __launch_bounds__(256) void rope_split_kernel(
    const float* __restrict__ qkv,
    float* __restrict__ Q, float* __restrict__ Kd, float* __restrict__ V)
{
    int gid = blockIdx.x * blockDim.x + threadIdx.x;
    int d = gid & 127;
    int t = (gid >> 7) & 511;
    int h = (gid >> 16) & 15;
    int b = gid >> 20;

    size_t base = ((size_t)(b * SEQ_ + t)) * QKVN_ + h * HD_;
    size_t oidx = ((size_t)((b * NH_ + h) * SEQ_ + t)) * HD_ + d;

    V[oidx] = tf32r(qkv[base + 2 * DIM_ + d]);

    float qv, kv;
    if (d < 16) {
        int i = (d < 8) ? d : d - 8;
        float inv = expf(-(float)i * (9.210340371976184f / 8.0f));
        float fr = (float)t * inv;
        float s, c;
        sincosf(fr, &s, &c);
        float q1 = qkv[base + i],         q2 = qkv[base + i + 8];
        float k1 = qkv[base + DIM_ + i],  k2 = qkv[base + DIM_ + i + 8];
        if (d < 8) { qv = q1 * c - q2 * s; kv = k1 * c - k2 * s; }
        else       { qv = q2 * c + q1 * s; kv = k2 * c + k1 * s; }
    } else {
        qv = qkv[base + d];
        kv = qkv[base + DIM_ + d];
    }
    Q[oidx] = tf32r(qv * 0.08838834764831845f);
    Kd[oidx] = tf32r(kv);
}

// ============================================================
// Tensor-core flash attention, cp.async 3-stage K/V ring, causal.
// grid (4, 256), 256 threads (8 warps). Q tile 128 rows; K/V chunks 32.
// Q/K/V pre-rounded tf32. Qs/Ks stride 132, Vs 136, P 76.
// ============================================================
#define AQ_STRIDE 132
#define AK_STRIDE 132
#define AV_STRIDE 136
#define AP_STRIDE 76
#define AQ_U32 (128 * AQ_STRIDE)          // 16896
#define AK_U32 (32 * AK_STRIDE)           // 4224 per stage
#define AV_U32 (32 * AV_STRIDE)           // 4352 per stage
#define AK_OFF AQ_U32
#define AV_OFF (AQ_U32 + 3 * AK_U32)
#define AP_OFF (AV_OFF + 3 * AV_U32)      // 42624
#define ATT_SMEM_BYTES ((AP_OFF + 8 * 16 * AP_STRIDE) * 4)   // 209408

__global__ __launch_bounds__(256, 1) void attn_mma_kernel(
    const float* __restrict__ Q, const float* __restrict__ K,
    const float* __restrict__ V, float* __restrict__ Y)
{
    const uint32_t sbase = smem_u32(dyn_smem);
    uint32_t* smu = (uint32_t*)dyn_smem;

    const int qt = blockIdx.x, bh = blockIdx.y;
    const int tid = threadIdx.x;
    const int lane = tid & 31;
    const int w = tid >> 5;
    const int grp = lane >> 2;
    const int qid = lane & 3;

    const float* Qh = Q + (size_t)bh * SEQ_ * HD_ + (size_t)qt * 128 * HD_;
    const float* Kh = K + (size_t)bh * SEQ_ * HD_;
    const float* Vh = V + (size_t)bh * SEQ_ * HD_;

    const int nch = 4 * qt + 4;

    auto issue_kv = [&](int kc, int s) {
        const uint32_t ks = sbase + (uint32_t)(AK_OFF + s * AK_U32) * 4;
        const uint32_t vs = sbase + (uint32_t)(AV_OFF + s * AV_U32) * 4;
#pragma unroll
        for (int i = 0; i < 4; i++) {
            int cidx = tid + i * 256;           // 0..1023 : 32 rows x 32 chunks
            int r = cidx >> 5, c4 = cidx & 31;
            const float* src = Kh + (size_t)(kc * 32 + r) * HD_ + c4 * 4;
            cp16(ks + (uint32_t)(r * AK_STRIDE + c4 * 4) * 4, src);
        }
#pragma unroll
        for (int i = 0; i < 4; i++) {
            int cidx = tid + i * 256;
            int r = cidx >> 5, c4 = cidx & 31;
            const float* src = Vh + (size_t)(kc * 32 + r) * HD_ + c4 * 4;
            cp16(vs + (uint32_t)(r * AV_STRIDE + c4 * 4) * 4, src);
        }
        CP_COMMIT();
    };

    // group 0: Q tile + KV chunk 0 ; group 1: KV chunk 1
    {
#pragma unroll
        for (int i = 0; i < 4; i++) {
            int cidx = tid + i * 256;           // 0..1023 of 4096: do 4 rounds
#pragma unroll
            for (int rr = 0; rr < 4; rr++) {
                int idx = cidx + rr * 1024;     // 128 rows x 32 chunks
                int r = idx >> 5, c4 = idx & 31;
                cp16(sbase + (uint32_t)(r * AQ_STRIDE + c4 * 4) * 4,
                     Qh + (size_t)r * HD_ + c4 * 4);
            }
        }
        // fold KV0 into group 0
#pragma unroll
        for (int i = 0; i < 4; i++) {
            int cidx = tid + i * 256;
            int r = cidx >> 5, c4 = cidx & 31;
            cp16(sbase + (uint32_t)(AK_OFF + r * AK_STRIDE + c4 * 4) * 4,
                 Kh + (size_t)r * HD_ + c4 * 4);
            cp16(sbase + (uint32_t)(AV_OFF + r * AV_STRIDE + c4 * 4) * 4,
                 Vh + (size_t)r * HD_ + c4 * 4);
        }
        CP_COMMIT();
        issue_kv(1, 1);
    }

    uint32_t* Pw = smu + AP_OFF + w * 16 * AP_STRIDE;
    const uint32_t* Qs = smu;

    float o[16][4];
#pragma unroll
    for (int j = 0; j < 16; j++)
#pragma unroll
        for (int q = 0; q < 4; q++) o[j][q] = 0.f;
    float m0 = -1e30f, m1 = -1e30f, l0 = 0.f, l1 = 0.f;

    const int r0g = qt * 128 + w * 16 + grp;
    const int r1g = r0g + 8;
    const int qrow = w * 16 + grp;

    for (int kc = 0; kc < nch; kc++) {
        if (kc + 1 < nch) { CP_WAIT(1); } else { CP_WAIT(0); }
        __syncthreads();

        const uint32_t* Ksb = smu + AK_OFF + (kc % 3) * AK_U32;
        const uint32_t* Vsb = smu + AV_OFF + (kc % 3) * AV_U32;

        // ---- S = Q_w @ K^T  (16 x 32) ----
        float s[4][4];
#pragma unroll
        for (int j = 0; j < 4; j++)
#pragma unroll
            for (int q = 0; q < 4; q++) s[j][q] = 0.f;

#pragma unroll
        for (int kk = 0; kk < 16; kk++) {
            uint32_t a[4];
            const uint32_t* qb = Qs + qrow * AQ_STRIDE + kk * 8;
            a[0] = qb[qid];
            a[1] = qb[8 * AQ_STRIDE + qid];
            a[2] = qb[qid + 4];
            a[3] = qb[8 * AQ_STRIDE + qid + 4];
#pragma unroll
            for (int j = 0; j < 4; j++) {
                uint32_t b[2];
                const uint32_t* kb = Ksb + (j * 8 + grp) * AK_STRIDE + kk * 8;
                b[0] = kb[qid];
                b[1] = kb[qid + 4];
                mma_tf32(s[j], a, b);
            }
        }

        // ---- causal mask ----
        const int cbase = kc * 32;
#pragma unroll
        for (int j = 0; j < 4; j++) {
            const int c0 = cbase + j * 8 + 2 * qid;
            if (c0 > r0g)     s[j][0] = -1e30f;
            if (c0 + 1 > r0g) s[j][1] = -1e30f;
            if (c0 > r1g)     s[j][2] = -1e30f;
            if (c0 + 1 > r1g) s[j][3] = -1e30f;
        }

        // ---- online softmax ----
        float mc0 = -1e30f, mc1 = -1e30f;
#pragma unroll
        for (int j = 0; j < 4; j++) {
            mc0 = fmaxf(mc0, fmaxf(s[j][0], s[j][1]));
            mc1 = fmaxf(mc1, fmaxf(s[j][2], s[j][3]));
        }
        mc0 = fmaxf(mc0, __shfl_xor_sync(0xFFFFFFFF, mc0, 1));
        mc0 = fmaxf(mc0, __shfl_xor_sync(0xFFFFFFFF, mc0, 2));
        mc1 = fmaxf(mc1, __shfl_xor_sync(0xFFFFFFFF, mc1, 1));
        mc1 = fmaxf(mc1, __shfl_xor_sync(0xFFFFFFFF, mc1, 2));

        const float mn0 = fmaxf(m0, mc0);
        const float mn1 = fmaxf(m1, mc1);
        const float corr0 = __expf(m0 - mn0);
        const float corr1 = __expf(m1 - mn1);
        m0 = mn0; m1 = mn1;

        float ls0 = 0.f, ls1 = 0.f;
#pragma unroll
        for (int j = 0; j < 4; j++) {
            s[j][0] = __expf(s[j][0] - mn0);
            s[j][1] = __expf(s[j][1] - mn0);
            s[j][2] = __expf(s[j][2] - mn1);
            s[j][3] = __expf(s[j][3] - mn1);
            ls0 += s[j][0] + s[j][1];
            ls1 += s[j][2] + s[j][3];
        }
        ls0 += __shfl_xor_sync(0xFFFFFFFF, ls0, 1);
        ls0 += __shfl_xor_sync(0xFFFFFFFF, ls0, 2);
        ls1 += __shfl_xor_sync(0xFFFFFFFF, ls1, 1);
        ls1 += __shfl_xor_sync(0xFFFFFFFF, ls1, 2);
        l0 = l0 * corr0 + ls0;
        l1 = l1 * corr1 + ls1;

#pragma unroll
        for (int j = 0; j < 16; j++) {
            o[j][0] *= corr0; o[j][1] *= corr0;
            o[j][2] *= corr1; o[j][3] *= corr1;
        }

        // ---- P (tf32) -> per-warp SMEM ----
#pragma unroll
        for (int j = 0; j < 4; j++) {
            uint32_t* p0 = Pw + grp * AP_STRIDE + j * 8 + 2 * qid;
            p0[0] = f2tf32(s[j][0]);
            p0[1] = f2tf32(s[j][1]);
            uint32_t* p1 = p0 + 8 * AP_STRIDE;
            p1[0] = f2tf32(s[j][2]);
            p1[1] = f2tf32(s[j][3]);
        }
        __syncwarp();

        // ---- O += P @ V ----
#pragma unroll
        for (int kk = 0; kk < 4; kk++) {
            uint32_t a[4];
            const uint32_t* pb = Pw + grp * AP_STRIDE + kk * 8;
            a[0] = pb[qid];
            a[1] = pb[8 * AP_STRIDE + qid];
            a[2] = pb[qid + 4];
            a[3] = pb[8 * AP_STRIDE + qid + 4];
#pragma unroll
            for (int j = 0; j < 16; j++) {
                uint32_t b[2];
                const uint32_t* vb = Vsb + (kk * 8 + qid) * AV_STRIDE + j * 8 + grp;
                b[0] = vb[0];
                b[1] = vb[4 * AV_STRIDE];
                mma_tf32(o[j], a, b);
            }
        }
        __syncwarp();

        if (kc + 2 < nch) issue_kv(kc + 2, (kc + 2) % 3);
    }

    // ---- write Y (B,T,C), tf32-rounded for GEMM2 ----
    const float inv0 = 1.f / l0;
    const float inv1 = 1.f / l1;
    const int b = bh >> 4, h = bh & 15;
    float* y0 = Y + ((size_t)(b * SEQ_ + r0g)) * DIM_ + h * HD_;
    float* y1 = Y + ((size_t)(b * SEQ_ + r1g)) * DIM_ + h * HD_;
#pragma unroll
    for (int j = 0; j < 16; j++) {
        const int col = j * 8 + 2 * qid;
        *(float2*)(y0 + col) = make_float2(tf32r(o[j][0] * inv0), tf32r(o[j][1] * inv0));
        *(float2*)(y1 + col) = make_float2(tf32r(o[j][2] * inv1), tf32r(o[j][3] * inv1));
    }
}

// ============================================================
// launch
// ============================================================
extern "C" void kernel_launch(void* const* d_in, const int* in_sizes, int n_in,
                              void* d_out, int out_size)
{
    const float* x    = (const float*)d_in[0];
    const float* Wqkv = (const float*)d_in[1];
    const float* Wout = (const float*)d_in[2];
    float* out = (float*)d_out;

    float *qkv, *Q, *K, *V, *Y, *xr, *wqkvr, *woutr;
    cudaGetSymbolAddress((void**)&qkv, g_qkv);
    cudaGetSymbolAddress((void**)&Q, g_q);
    cudaGetSymbolAddress((void**)&K, g_k);
    cudaGetSymbolAddress((void**)&V, g_v);
    cudaGetSymbolAddress((void**)&Y, g_y);
    cudaGetSymbolAddress((void**)&xr, g_xr);
    cudaGetSymbolAddress((void**)&wqkvr, g_wqkvr);
    cudaGetSymbolAddress((void**)&woutr, g_woutr);

    cudaFuncSetAttribute(tf32_gemm_async, cudaFuncAttributeMaxDynamicSharedMemorySize, GEMM_SMEM_BYTES);
    cudaFuncSetAttribute(attn_mma_kernel, cudaFuncAttributeMaxDynamicSharedMemorySize, ATT_SMEM_BYTES);

    // 0) pre-round operands to tf32
    round_tf32_kernel<<<(ROWS_*DIM_/4 + 255)/256, 256>>>((const float4*)x, (float4*)xr, ROWS_*DIM_/4);
    round_tf32_kernel<<<(DIM_*QKVN_/4 + 255)/256, 256>>>((const float4*)Wqkv, (float4*)wqkvr, DIM_*QKVN_/4);
    round_tf32_kernel<<<(DIM_*DIM_/4 + 255)/256, 256>>>((const float4*)Wout, (float4*)woutr, DIM_*DIM_/4);

    // 1) qkv = x @ Wqkv
    tf32_gemm_async<<<dim3(QKVN_ / 128, ROWS_ / 128), 256, GEMM_SMEM_BYTES>>>(xr, wqkvr, qkv, ROWS_, QKVN_, DIM_);

    // 2) split + rope (+ scale folded into Q), outputs tf32-rounded
    rope_split_kernel<<<(BATCH_ * NH_ * SEQ_ * HD_) / 256, 256>>>(qkv, Q, K, V);

    // 3) causal attention -> Y (tf32-rounded)
    attn_mma_kernel<<<dim3(SEQ_ / 128, BATCH_ * NH_), 256, ATT_SMEM_BYTES>>>(Q, K, V, Y);

    // 4) out = Y @ Wout
    tf32_gemm_async<<<dim3(DIM_ / 128, ROWS_ / 128), 256, GEMM_SMEM_BYTES>>>(Y, woutr, out, ROWS_, DIM_, DIM_);
}

// round 8
// speedup vs baseline: 4.1731x; 1.0069x over previous
#include <cuda_runtime.h>
#include <math.h>
#include <cstdint>

#define BATCH_ 16
#define SEQ_ 512
#define DIM_ 2048
#define NH_ 16
#define HD_ 128
#define ROWS_ (BATCH_*SEQ_)    // 8192
#define QKVN_ (3*DIM_)         // 6144

// ---- scratch (static device globals; no runtime allocation) ----
__device__ float g_qkv[(size_t)ROWS_ * QKVN_];
__device__ float g_q[(size_t)BATCH_*NH_*SEQ_*HD_];
__device__ float g_k[(size_t)BATCH_*NH_*SEQ_*HD_];
__device__ float g_v[(size_t)BATCH_*NH_*SEQ_*HD_];
__device__ float g_y[(size_t)ROWS_ * DIM_];
__device__ float g_xr[(size_t)ROWS_ * DIM_];       // tf32-rounded x
__device__ float g_wqkvr[(size_t)DIM_ * QKVN_];    // tf32-rounded Wqkv
__device__ float g_woutr[(size_t)DIM_ * DIM_];     // tf32-rounded Wout

extern __shared__ char dyn_smem[];

// ============================================================
// helpers
// ============================================================
__device__ __forceinline__ uint32_t f2tf32(float f) {
    uint32_t r;
    asm("cvt.rna.tf32.f32 %0, %1;" : "=r"(r) : "f"(f));
    return r;
}
__device__ __forceinline__ float tf32r(float f) { return __uint_as_float(f2tf32(f)); }

__device__ __forceinline__ void mma_tf32(float* c, const uint32_t* a, const uint32_t* b) {
    asm volatile(
        "mma.sync.aligned.m16n8k8.row.col.f32.tf32.tf32.f32 "
        "{%0,%1,%2,%3}, {%4,%5,%6,%7}, {%8,%9}, {%0,%1,%2,%3};"
        : "+f"(c[0]), "+f"(c[1]), "+f"(c[2]), "+f"(c[3])
        : "r"(a[0]), "r"(a[1]), "r"(a[2]), "r"(a[3]), "r"(b[0]), "r"(b[1]));
}

__device__ __forceinline__ uint32_t smem_u32(const void* p) {
    uint32_t a;
    asm("{ .reg .u64 t; cvta.to.shared.u64 t, %1; cvt.u32.u64 %0, t; }" : "=r"(a) : "l"(p));
    return a;
}
__device__ __forceinline__ void cp16(uint32_t dst, const void* src) {
    asm volatile("cp.async.cg.shared.global [%0], [%1], 16;" :: "r"(dst), "l"(src) : "memory");
}
#define CP_COMMIT() asm volatile("cp.async.commit_group;" ::: "memory")
#define CP_WAIT(n)  asm volatile("cp.async.wait_group %0;" :: "n"(n) : "memory")

// ============================================================
// tf32 rounding (elementwise, float4)
// ============================================================
__global__ __launch_bounds__(256) void round_tf32_kernel(
    const float4* __restrict__ in, float4* __restrict__ out, int n4)
{
    int i = blockIdx.x * blockDim.x + threadIdx.x;
    if (i < n4) {
        float4 v = in[i];
        v.x = tf32r(v.x); v.y = tf32r(v.y); v.z = tf32r(v.z); v.w = tf32r(v.w);
        out[i] = v;
    }
}

// ============================================================
// TF32 GEMM, cp.async 3-stage (unchanged from round 7; tensor=62.5%)
// ============================================================
#define GA_STRIDE 36
#define GB_STRIDE 136
#define GA_U32 (128 * GA_STRIDE)
#define GB_U32 (32 * GB_STRIDE)
#define GSTAGE_U32 (GA_U32 + GB_U32)
#define GEMM_SMEM_BYTES (3 * GSTAGE_U32 * 4)

__global__ __launch_bounds__(256) void tf32_gemm_async(
    const float* __restrict__ A, const float* __restrict__ B,
    float* __restrict__ C, int M, int N, int K)
{
    const uint32_t sbase = smem_u32(dyn_smem);
    uint32_t* smu = (uint32_t*)dyn_smem;

    const int tid = threadIdx.x;
    const int lane = tid & 31;
    const int w = tid >> 5;
    const int wm = (w & 1) * 64;
    const int wn = (w >> 1) * 32;
    const int grp = lane >> 2;
    const int qid = lane & 3;

    const int bm = blockIdx.y, bn = blockIdx.x;
    const float* Ab = A + (size_t)bm * 128 * K;
    const float* Bb = B + (size_t)bn * 128;

    const int nch = K / 32;

    auto issue = [&](int ch, int s) {
        const uint32_t sa = sbase + (uint32_t)(s * GSTAGE_U32) * 4;
        const uint32_t sb = sa + GA_U32 * 4;
#pragma unroll
        for (int i = 0; i < 4; i++) {
            int cidx = tid + i * 256;
            int r = cidx >> 3, c4 = cidx & 7;
            cp16(sa + (uint32_t)(r * GA_STRIDE + c4 * 4) * 4,
                 Ab + (size_t)r * K + ch * 32 + c4 * 4);
        }
#pragma unroll
        for (int i = 0; i < 4; i++) {
            int cidx = tid + i * 256;
            int r = cidx >> 5, c4 = cidx & 31;
            cp16(sb + (uint32_t)(r * GB_STRIDE + c4 * 4) * 4,
                 Bb + (size_t)(ch * 32 + r) * N + c4 * 4);
        }
        CP_COMMIT();
    };

    float c[4][4][4];
#pragma unroll
    for (int i = 0; i < 4; i++)
#pragma unroll
        for (int j = 0; j < 4; j++)
#pragma unroll
            for (int q = 0; q < 4; q++) c[i][j][q] = 0.f;

    issue(0, 0);
    issue(1, 1);

    for (int ch = 0; ch < nch; ch++) {
        if (ch + 1 < nch) { CP_WAIT(1); } else { CP_WAIT(0); }
        __syncthreads();

        const uint32_t* As = smu + (ch % 3) * GSTAGE_U32;
        const uint32_t* Bs = As + GA_U32;
#pragma unroll
        for (int ks = 0; ks < 4; ks++) {
            const int kk = ks * 8;
            uint32_t af[4][4], bf[4][2];
#pragma unroll
            for (int i = 0; i < 4; i++) {
                const int m = wm + i * 16 + grp;
                af[i][0] = As[m * GA_STRIDE + kk + qid];
                af[i][1] = As[(m + 8) * GA_STRIDE + kk + qid];
                af[i][2] = As[m * GA_STRIDE + kk + qid + 4];
                af[i][3] = As[(m + 8) * GA_STRIDE + kk + qid + 4];
            }
#pragma unroll
            for (int j = 0; j < 4; j++) {
                const int n = wn + j * 8 + grp;
                bf[j][0] = Bs[(kk + qid) * GB_STRIDE + n];
                bf[j][1] = Bs[(kk + qid + 4) * GB_STRIDE + n];
            }
#pragma unroll
            for (int i = 0; i < 4; i++)
#pragma unroll
                for (int j = 0; j < 4; j++)
                    mma_tf32(c[i][j], af[i], bf[j]);
        }

        if (ch + 2 < nch) issue(ch + 2, (ch + 2) % 3);
    }

#pragma unroll
    for (int i = 0; i < 4; i++) {
        const int row = bm * 128 + wm + i * 16 + grp;
#pragma unroll
        for (int j = 0; j < 4; j++) {
            const int col = bn * 128 + wn + j * 8 + qid * 2;
            *(float2*)(C + (size_t)row * N + col)       = make_float2(c[i][j][0], c[i][j][1]);
            *(float2*)(C + (size_t)(row + 8) * N + col) = make_float2(c[i][j][2], c[i][j][3]);
        }
    }
}

// ============================================================
// RoPE + split -> Q,K,V in [B,H,T,hd], tf32-rounded, Q pre-scaled.
// ============================================================
__global__ __launch_bounds__(256) void rope_split_kernel(
    const float* __restrict__ qkv,
    float* __restrict__ Q, float* __restrict__ Kd, float* __restrict__ V)
{
    int gid = blockIdx.x * blockDim.x + threadIdx.x;
    int d = gid & 127;
    int t = (gid >> 7) & 511;
    int h = (gid >> 16) & 15;
    int b = gid >> 20;

    size_t base = ((size_t)(b * SEQ_ + t)) * QKVN_ + h * HD_;
    size_t oidx = ((size_t)((b * NH_ + h) * SEQ_ + t)) * HD_ + d;

    V[oidx] = tf32r(qkv[base + 2 * DIM_ + d]);

    float qv, kv;
    if (d < 16) {
        int i = (d < 8) ? d : d - 8;
        float inv = expf(-(float)i * (9.210340371976184f / 8.0f));
        float fr = (float)t * inv;
        float s, c;
        sincosf(fr, &s, &c);
        float q1 = qkv[base + i],         q2 = qkv[base + i + 8];
        float k1 = qkv[base + DIM_ + i],  k2 = qkv[base + DIM_ + i + 8];
        if (d < 8) { qv = q1 * c - q2 * s; kv = k1 * c - k2 * s; }
        else       { qv = q2 * c + q1 * s; kv = k2 * c + k1 * s; }
    } else {
        qv = qkv[base + d];
        kv = qkv[base + DIM_ + d];
    }
    Q[oidx] = tf32r(qv * 0.08838834764831845f);
    Kd[oidx] = tf32r(kv);
}

// ============================================================
// Tensor-core flash attention v3: Q in registers, 64-row K/V
// chunks, 2-stage cp.async ring. grid (4, 256), 256 threads.
// SMEM: K[2][64][132], V[2][64][136], P[8][16][76] = 176128 B.
// Q staged once through the K-ring region (exactly 128*132 u32).
// ============================================================
#define AK_STRIDE 132
#define AV_STRIDE 136
#define AP_STRIDE 76
#define AK_U32 (64 * AK_STRIDE)           // 8448 per stage
#define AV_U32 (64 * AV_STRIDE)           // 8704 per stage
#define AV_OFF (2 * AK_U32)               // 16896
#define AP_OFF (AV_OFF + 2 * AV_U32)      // 34304
#define ATT_SMEM_BYTES ((AP_OFF + 8 * 16 * AP_STRIDE) * 4)   // 176128

__global__ __launch_bounds__(256, 1) void attn_mma_kernel(
    const float* __restrict__ Q, const float* __restrict__ K,
    const float* __restrict__ V, float* __restrict__ Y)
{
    const uint32_t sbase = smem_u32(dyn_smem);
    uint32_t* smu = (uint32_t*)dyn_smem;

    const int qt = blockIdx.x, bh = blockIdx.y;
    const int tid = threadIdx.x;
    const int lane = tid & 31;
    const int w = tid >> 5;
    const int grp = lane >> 2;
    const int qid = lane & 3;

    const float* Qh = Q + (size_t)bh * SEQ_ * HD_ + (size_t)qt * 128 * HD_;
    const float* Kh = K + (size_t)bh * SEQ_ * HD_;
    const float* Vh = V + (size_t)bh * SEQ_ * HD_;

    const int nch = 2 * qt + 2;     // 64-row chunks

    // ---- stage Q (128x128) into K-ring region, extract fragments ----
    uint32_t qf[16][4];
    {
#pragma unroll
        for (int i = 0; i < 16; i++) {
            int idx = tid + i * 256;            // 128 rows x 32 float4
            int r = idx >> 5, c4 = idx & 31;
            cp16(sbase + (uint32_t)(r * AK_STRIDE + c4 * 4) * 4,
                 Qh + (size_t)r * HD_ + c4 * 4);
        }
        CP_COMMIT();
        CP_WAIT(0);
        __syncthreads();
        const int qrow = w * 16 + grp;
#pragma unroll
        for (int kk = 0; kk < 16; kk++) {
            const uint32_t* qb = smu + qrow * AK_STRIDE + kk * 8;
            qf[kk][0] = qb[qid];
            qf[kk][1] = qb[8 * AK_STRIDE + qid];
            qf[kk][2] = qb[qid + 4];
            qf[kk][3] = qb[8 * AK_STRIDE + qid + 4];
        }
        __syncthreads();
    }

    auto issue_kv = [&](int kc, int s) {
        const uint32_t ks = sbase + (uint32_t)(s * AK_U32) * 4;
        const uint32_t vs = sbase + (uint32_t)(AV_OFF + s * AV_U32) * 4;
#pragma unroll
        for (int i = 0; i < 8; i++) {
            int cidx = tid + i * 256;           // 64 rows x 32 chunks
            int r = cidx >> 5, c4 = cidx & 31;
            cp16(ks + (uint32_t)(r * AK_STRIDE + c4 * 4) * 4,
                 Kh + (size_t)(kc * 64 + r) * HD_ + c4 * 4);
            cp16(vs + (uint32_t)(r * AV_STRIDE + c4 * 4) * 4,
                 Vh + (size_t)(kc * 64 + r) * HD_ + c4 * 4);
        }
        CP_COMMIT();
    };

    issue_kv(0, 0);
    issue_kv(1, 1);

    uint32_t* Pw = smu + AP_OFF + w * 16 * AP_STRIDE;

    float o[16][4];
#pragma unroll
    for (int j = 0; j < 16; j++)
#pragma unroll
        for (int q = 0; q < 4; q++) o[j][q] = 0.f;
    float m0 = -1e30f, m1 = -1e30f, l0 = 0.f, l1 = 0.f;

    const int r0g = qt * 128 + w * 16 + grp;
    const int r1g = r0g + 8;

    for (int kc = 0; kc < nch; kc++) {
        if (kc + 1 < nch) { CP_WAIT(1); } else { CP_WAIT(0); }
        __syncthreads();

        const uint32_t* Ksb = smu + (kc & 1) * AK_U32;
        const uint32_t* Vsb = smu + AV_OFF + (kc & 1) * AV_U32;

        // ---- S = Q_w @ K^T  (16 x 64) ----
        float s[8][4];
#pragma unroll
        for (int j = 0; j < 8; j++)
#pragma unroll
            for (int q = 0; q < 4; q++) s[j][q] = 0.f;

#pragma unroll
        for (int kk = 0; kk < 16; kk++) {
#pragma unroll
            for (int j = 0; j < 8; j++) {
                uint32_t b[2];
                const uint32_t* kb = Ksb + (j * 8 + grp) * AK_STRIDE + kk * 8;
                b[0] = kb[qid];
                b[1] = kb[qid + 4];
                mma_tf32(s[j], qf[kk], b);
            }
        }

        // ---- causal mask ----
        const int cbase = kc * 64;
#pragma unroll
        for (int j = 0; j < 8; j++) {
            const int c0 = cbase + j * 8 + 2 * qid;
            if (c0 > r0g)     s[j][0] = -1e30f;
            if (c0 + 1 > r0g) s[j][1] = -1e30f;
            if (c0 > r1g)     s[j][2] = -1e30f;
            if (c0 + 1 > r1g) s[j][3] = -1e30f;
        }

        // ---- online softmax ----
        float mc0 = -1e30f, mc1 = -1e30f;
#pragma unroll
        for (int j = 0; j < 8; j++) {
            mc0 = fmaxf(mc0, fmaxf(s[j][0], s[j][1]));
            mc1 = fmaxf(mc1, fmaxf(s[j][2], s[j][3]));
        }
        mc0 = fmaxf(mc0, __shfl_xor_sync(0xFFFFFFFF, mc0, 1));
        mc0 = fmaxf(mc0, __shfl_xor_sync(0xFFFFFFFF, mc0, 2));
        mc1 = fmaxf(mc1, __shfl_xor_sync(0xFFFFFFFF, mc1, 1));
        mc1 = fmaxf(mc1, __shfl_xor_sync(0xFFFFFFFF, mc1, 2));

        const float mn0 = fmaxf(m0, mc0);
        const float mn1 = fmaxf(m1, mc1);
        const float corr0 = __expf(m0 - mn0);
        const float corr1 = __expf(m1 - mn1);
        m0 = mn0; m1 = mn1;

        float ls0 = 0.f, ls1 = 0.f;
#pragma unroll
        for (int j = 0; j < 8; j++) {
            s[j][0] = __expf(s[j][0] - mn0);
            s[j][1] = __expf(s[j][1] - mn0);
            s[j][2] = __expf(s[j][2] - mn1);
            s[j][3] = __expf(s[j][3] - mn1);
            ls0 += s[j][0] + s[j][1];
            ls1 += s[j][2] + s[j][3];
        }
        ls0 += __shfl_xor_sync(0xFFFFFFFF, ls0, 1);
        ls0 += __shfl_xor_sync(0xFFFFFFFF, ls0, 2);
        ls1 += __shfl_xor_sync(0xFFFFFFFF, ls1, 1);
        ls1 += __shfl_xor_sync(0xFFFFFFFF, ls1, 2);
        l0 = l0 * corr0 + ls0;
        l1 = l1 * corr1 + ls1;

#pragma unroll
        for (int j = 0; j < 16; j++) {
            o[j][0] *= corr0; o[j][1] *= corr0;
            o[j][2] *= corr1; o[j][3] *= corr1;
        }

        // ---- P (tf32) -> per-warp SMEM ----
#pragma unroll
        for (int j = 0; j < 8; j++) {
            uint32_t* p0 = Pw + grp * AP_STRIDE + j * 8 + 2 * qid;
            p0[0] = f2tf32(s[j][0]);
            p0[1] = f2tf32(s[j][1]);
            uint32_t* p1 = p0 + 8 * AP_STRIDE;
            p1[0] = f2tf32(s[j][2]);
            p1[1] = f2tf32(s[j][3]);
        }
        __syncwarp();

        // ---- O += P @ V ----
#pragma unroll
        for (int kk = 0; kk < 8; kk++) {
            uint32_t a[4];
            const uint32_t* pb = Pw + grp * AP_STRIDE + kk * 8;
            a[0] = pb[qid];
            a[1] = pb[8 * AP_STRIDE + qid];
            a[2] = pb[qid + 4];
            a[3] = pb[8 * AP_STRIDE + qid + 4];
#pragma unroll
            for (int j = 0; j < 16; j++) {
                uint32_t b[2];
                const uint32_t* vb = Vsb + (kk * 8 + qid) * AV_STRIDE + j * 8 + grp;
                b[0] = vb[0];
                b[1] = vb[4 * AV_STRIDE];
                mma_tf32(o[j], a, b);
            }
        }

        __syncthreads();    // all warps done with buffer (kc&1) before refill
        if (kc + 2 < nch) issue_kv(kc + 2, kc & 1);
    }

    // ---- write Y (B,T,C), tf32-rounded for GEMM2 ----
    const float inv0 = 1.f / l0;
    const float inv1 = 1.f / l1;
    const int b = bh >> 4, h = bh & 15;
    float* y0 = Y + ((size_t)(b * SEQ_ + r0g)) * DIM_ + h * HD_;
    float* y1 = Y + ((size_t)(b * SEQ_ + r1g)) * DIM_ + h * HD_;
#pragma unroll
    for (int j = 0; j < 16; j++) {
        const int col = j * 8 + 2 * qid;
        *(float2*)(y0 + col) = make_float2(tf32r(o[j][0] * inv0), tf32r(o[j][1] * inv0));
        *(float2*)(y1 + col) = make_float2(tf32r(o[j][2] * inv1), tf32r(o[j][3] * inv1));
    }
}

// ============================================================
// launch
// ============================================================
extern "C" void kernel_launch(void* const* d_in, const int* in_sizes, int n_in,
                              void* d_out, int out_size)
{
    const float* x    = (const float*)d_in[0];
    const float* Wqkv = (const float*)d_in[1];
    const float* Wout = (const float*)d_in[2];
    float* out = (float*)d_out;

    float *qkv, *Q, *K, *V, *Y, *xr, *wqkvr, *woutr;
    cudaGetSymbolAddress((void**)&qkv, g_qkv);
    cudaGetSymbolAddress((void**)&Q, g_q);
    cudaGetSymbolAddress((void**)&K, g_k);
    cudaGetSymbolAddress((void**)&V, g_v);
    cudaGetSymbolAddress((void**)&Y, g_y);
    cudaGetSymbolAddress((void**)&xr, g_xr);
    cudaGetSymbolAddress((void**)&wqkvr, g_wqkvr);
    cudaGetSymbolAddress((void**)&woutr, g_woutr);

    cudaFuncSetAttribute(tf32_gemm_async, cudaFuncAttributeMaxDynamicSharedMemorySize, GEMM_SMEM_BYTES);
    cudaFuncSetAttribute(attn_mma_kernel, cudaFuncAttributeMaxDynamicSharedMemorySize, ATT_SMEM_BYTES);

    // 0) pre-round operands to tf32
    round_tf32_kernel<<<(ROWS_*DIM_/4 + 255)/256, 256>>>((const float4*)x, (float4*)xr, ROWS_*DIM_/4);
    round_tf32_kernel<<<(DIM_*QKVN_/4 + 255)/256, 256>>>((const float4*)Wqkv, (float4*)wqkvr, DIM_*QKVN_/4);
    round_tf32_kernel<<<(DIM_*DIM_/4 + 255)/256, 256>>>((const float4*)Wout, (float4*)woutr, DIM_*DIM_/4);

    // 1) qkv = x @ Wqkv
    tf32_gemm_async<<<dim3(QKVN_ / 128, ROWS_ / 128), 256, GEMM_SMEM_BYTES>>>(xr, wqkvr, qkv, ROWS_, QKVN_, DIM_);

    // 2) split + rope (+ scale folded into Q), outputs tf32-rounded
    rope_split_kernel<<<(BATCH_ * NH_ * SEQ_ * HD_) / 256, 256>>>(qkv, Q, K, V);

    // 3) causal attention -> Y (tf32-rounded)
    attn_mma_kernel<<<dim3(SEQ_ / 128, BATCH_ * NH_), 256, ATT_SMEM_BYTES>>>(Q, K, V, Y);

    // 4) out = Y @ Wout
    tf32_gemm_async<<<dim3(DIM_ / 128, ROWS_ / 128), 256, GEMM_SMEM_BYTES>>>(Y, woutr, out, ROWS_, DIM_, DIM_);
}